// round 1
// baseline (speedup 1.0000x reference)
#include <cuda_runtime.h>
#include <math.h>

#define N_ANCH 21840
#define NWORDS 342            // ceil(21840/64)
#define HPAIR  171            // NWORDS/2
#define NMS_THF 0.3f
#define CLS_THF 0.05f
#define FIN_THF 0.5f

// ---- static device scratch (no runtime allocation allowed) ----
__device__ float g_x1[N_ANCH], g_y1[N_ANCH], g_x2[N_ANCH], g_y2[N_ANCH];
__device__ float g_sc[N_ANCH], g_area[N_ANCH];
__device__ unsigned long long g_key[N_ANCH];
__device__ int   g_pos[N_ANCH];
__device__ float g_sx1[N_ANCH], g_sy1[N_ANCH], g_sx2[N_ANCH], g_sy2[N_ANCH], g_sarea[N_ANCH];
__device__ unsigned char g_sval[N_ANCH];
__device__ unsigned char g_keep[N_ANCH];
__device__ unsigned long long g_mask[(size_t)N_ANCH * NWORDS];  // ~60MB, fits L2

struct InPtrs { const float* cls[6]; const float* reg[6]; };

// ---------------- K1: decode ----------------
__global__ void k_decode(InPtrs in) {
    int i = blockIdx.x * blockDim.x + threadIdx.x;
    if (i >= N_ANCH) return;
    const int offs[7]   = {0, 16384, 20480, 21504, 21760, 21824, 21840};
    const int maps[6]   = {128, 64, 32, 16, 8, 4};
    const float strd[6] = {4.f, 8.f, 16.f, 32.f, 64.f, 128.f};
    int sc = 0;
    #pragma unroll
    for (int k = 0; k < 5; k++) if (i >= offs[k + 1]) sc = k + 1;
    int local = i - offs[sc];
    int W = maps[sc];
    int y = local / W, x = local - y * W;
    int HW = W * W;
    const float* cls = in.cls[sc];
    const float* reg = in.reg[sc];

    // softmax over 2 channels, exactly like jax.nn.softmax (max-sub form)
    float c0 = cls[local], c1 = cls[HW + local];
    float m  = fmaxf(c0, c1);
    float e0 = expf(__fsub_rn(c0, m));
    float e1 = expf(__fsub_rn(c1, m));
    float prob = __fdiv_rn(e1, __fadd_rn(e0, e1));

    float s   = strd[sc];
    float pwh = s * 4.0f;                 // exact
    float pcx = __fadd_rn(0.5f * s, __fmul_rn((float)x, s));
    float pcy = __fadd_rn(0.5f * s, __fmul_rn((float)y, s));
    float l0 = reg[local], l1 = reg[HW + local];
    float l2 = reg[2 * HW + local], l3 = reg[3 * HW + local];
    float cx = __fadd_rn(pcx, __fmul_rn(__fmul_rn(l0, 0.1f), pwh));
    float cy = __fadd_rn(pcy, __fmul_rn(__fmul_rn(l1, 0.1f), pwh));
    float w  = __fmul_rn(pwh, expf(__fmul_rn(l2, 0.2f)));
    float h  = __fmul_rn(pwh, expf(__fmul_rn(l3, 0.2f)));
    float x1 = __fsub_rn(cx, __fmul_rn(w, 0.5f));  // w/2 is exact either way
    float y1 = __fsub_rn(cy, __fmul_rn(h, 0.5f));
    float x2 = __fadd_rn(x1, w);
    float y2 = __fadd_rn(y1, h);

    g_x1[i] = x1; g_y1[i] = y1; g_x2[i] = x2; g_y2[i] = y2; g_sc[i] = prob;
    g_area[i] = __fmul_rn(__fadd_rn(__fsub_rn(x2, x1), 1.0f),
                          __fadd_rn(__fsub_rn(y2, y1), 1.0f));

    bool valid = prob > CLS_THF;
    float ks = valid ? prob : __int_as_float(0xff800000);  // -inf
    unsigned int u   = __float_as_uint(ks);
    unsigned int ord = (u & 0x80000000u) ? ~u : (u | 0x80000000u);
    // ascending key == descending score, ties by ascending index (stable argsort(-scores))
    g_key[i] = ((unsigned long long)(~ord) << 32) | (unsigned int)i;
}

// ---------------- K2: O(N^2) rank sort + scatter ----------------
__global__ void k_rank() {
    __shared__ unsigned long long tile[256];
    int i = blockIdx.x * 256 + threadIdx.x;
    unsigned long long mykey = (i < N_ANCH) ? g_key[i] : 0ull;
    int cnt = 0;
    for (int tb = 0; tb < N_ANCH; tb += 256) {
        int j = tb + threadIdx.x;
        __syncthreads();
        tile[threadIdx.x] = (j < N_ANCH) ? g_key[j] : 0xFFFFFFFFFFFFFFFFull;
        __syncthreads();
        int lim = min(256, N_ANCH - tb);
        #pragma unroll 8
        for (int jj = 0; jj < lim; jj++) cnt += (tile[jj] < mykey) ? 1 : 0;
    }
    if (i < N_ANCH) {
        int pos = cnt;
        g_pos[i]    = pos;
        g_sx1[pos]  = g_x1[i];
        g_sy1[pos]  = g_y1[i];
        g_sx2[pos]  = g_x2[i];
        g_sy2[pos]  = g_y2[i];
        g_sarea[pos] = g_area[i];
        g_sval[pos] = (g_sc[i] > CLS_THF) ? 1 : 0;
    }
}

// ---------------- K3: pairwise suppression bitmask ----------------
__global__ void k_mask() {
    int cb = blockIdx.x, rb = blockIdx.y;
    if (cb < rb) return;   // only need j > i
    __shared__ float cx1[64], cy1[64], cx2[64], cy2[64], car[64];
    int t = threadIdx.x;
    int j0 = cb * 64;
    int j = j0 + t;
    if (j < N_ANCH) {
        cx1[t] = g_sx1[j]; cy1[t] = g_sy1[j];
        cx2[t] = g_sx2[j]; cy2[t] = g_sy2[j];
        car[t] = g_sarea[j];
    }
    __syncthreads();
    int i = rb * 64 + t;
    if (i >= N_ANCH) return;
    float x1 = g_sx1[i], y1 = g_sy1[i], x2 = g_sx2[i], y2 = g_sy2[i], ar = g_sarea[i];
    unsigned long long bits = 0;
    int lim = min(64, N_ANCH - j0);
    for (int jj = 0; jj < lim; jj++) {
        int jg = j0 + jj;
        if (jg <= i) continue;
        float xx1 = fmaxf(x1, cx1[jj]);
        float yy1 = fmaxf(y1, cy1[jj]);
        float xx2 = fminf(x2, cx2[jj]);
        float yy2 = fminf(y2, cy2[jj]);
        float w = fmaxf(__fadd_rn(__fsub_rn(xx2, xx1), 1.0f), 0.0f);
        float h = fmaxf(__fadd_rn(__fsub_rn(yy2, yy1), 1.0f), 0.0f);
        float inter = __fmul_rn(w, h);
        float denom = __fsub_rn(__fadd_rn(ar, car[jj]), inter);
        float iou = __fdiv_rn(inter, denom);
        bits |= ((unsigned long long)(iou > NMS_THF)) << jj;
    }
    g_mask[(size_t)i * NWORDS + cb] = bits;
}

// ---------------- K4: serial greedy scan (1 block) ----------------
__global__ void k_scan() {
    __shared__ unsigned long long removed[NWORDS];
    __shared__ unsigned long long validb[NWORDS];
    int t = threadIdx.x;
    if (t < NWORDS) {
        removed[t] = 0ull;
        unsigned long long v = 0ull;
        int base = t << 6;
        for (int b = 0; b < 64; b++) {
            int j = base + b;
            unsigned long long bit = (j < N_ANCH && g_sval[j]) ? 1ull : 0ull;
            v |= bit << b;
        }
        validb[t] = v;
    }
    __syncthreads();

    bool pown = (t < HPAIR);
    const ulonglong2* mask2 = (const ulonglong2*)g_mask;  // row base i*NWORDS is 16B aligned

    const int D = 8;   // prefetch depth; N_ANCH % 8 == 0
    ulonglong2 buf[D];
    #pragma unroll
    for (int s = 0; s < D; s++)
        buf[s] = pown ? mask2[(size_t)s * HPAIR + t] : make_ulonglong2(0ull, 0ull);

    for (int base = 0; base < N_ANCH; base += D) {
        #pragma unroll
        for (int s = 0; s < D; s++) {
            int i = base + s;
            ulonglong2 cur = buf[s];
            // prefetch row i+D, skipping rows already known removed (monotone)
            int nr = i + D;
            ulonglong2 nv = make_ulonglong2(0ull, 0ull);
            if (nr < N_ANCH && pown && (2 * t + 1) >= (nr >> 6)) {
                if (((removed[nr >> 6] >> (nr & 63)) & 1ull) == 0ull)
                    nv = mask2[(size_t)nr * HPAIR + t];
            }
            buf[s] = nv;

            int wi = i >> 6, bi = i & 63;
            bool act = (((removed[wi] >> bi) & 1ull) == 0ull) &&
                       (((validb[wi] >> bi) & 1ull) != 0ull);
            if (t == 0) g_keep[i] = (unsigned char)act;
            if (act) {   // uniform across block (bit bi of word wi is never set by row i's own mask)
                if (pown) {
                    if (2 * t     >= wi) removed[2 * t]     |= cur.x;
                    if (2 * t + 1 >= wi) removed[2 * t + 1] |= cur.y;
                }
                __syncthreads();
            }
        }
    }
}

// ---------------- K5: final masked write ----------------
__global__ void k_final(float* __restrict__ out) {
    int i = blockIdx.x * blockDim.x + threadIdx.x;
    if (i >= N_ANCH) return;
    float sc = g_sc[i];
    bool kp = (g_keep[g_pos[i]] != 0) && (sc > FIN_THF);
    float f = kp ? 1.0f : 0.0f;
    out[i * 5 + 0] = __fmul_rn(g_x1[i], f);
    out[i * 5 + 1] = __fmul_rn(g_y1[i], f);
    out[i * 5 + 2] = __fmul_rn(g_x2[i], f);
    out[i * 5 + 3] = __fmul_rn(g_y2[i], f);
    out[i * 5 + 4] = __fmul_rn(sc, f);
}

extern "C" void kernel_launch(void* const* d_in, const int* in_sizes, int n_in,
                              void* d_out, int out_size) {
    (void)in_sizes; (void)n_in; (void)out_size;
    InPtrs p;
    for (int i = 0; i < 6; i++) {
        p.cls[i] = (const float*)d_in[2 * i];
        p.reg[i] = (const float*)d_in[2 * i + 1];
    }
    k_decode<<<86, 256>>>(p);
    k_rank<<<86, 256>>>();
    dim3 gm(NWORDS, NWORDS);
    k_mask<<<gm, 64>>>();
    k_scan<<<1, 256>>>();
    k_final<<<86, 256>>>((float*)d_out);
}

// round 2
// speedup vs baseline: 10.9624x; 10.9624x over previous
#include <cuda_runtime.h>
#include <math.h>

#define N_ANCH 21840
#define NTILE  342            // ceil(21840/64)
#define NSTATE 683            // ceil(21840/32), 2 bits per box
#define NBLK   86             // ceil(21840/256)
#define CAP    192            // max higher-ranked suppressors stored per box
#define NMS_THF 0.3f
#define CLS_THF 0.05f
#define FIN_THF 0.5f
#define FULLM 0xFFFFFFFFu

// ---- static device scratch ----
__device__ float g_x1[N_ANCH], g_y1[N_ANCH], g_x2[N_ANCH], g_y2[N_ANCH];
__device__ float g_sc[N_ANCH], g_area[N_ANCH];
__device__ unsigned g_keyA[N_ANCH], g_keyB[N_ANCH];
__device__ unsigned short g_valA[N_ANCH], g_valB[N_ANCH];
__device__ int g_hist[NBLK * 256], g_off[NBLK * 256];
__device__ int g_srank[N_ANCH];
__device__ float g_tminx1[NTILE], g_tminy1[NTILE], g_tmaxx2[NTILE], g_tmaxy2[NTILE];
__device__ float g_tamin[NTILE], g_tamax[NTILE];
__device__ unsigned short g_nbr[(size_t)N_ANCH * CAP];
__device__ int g_ncnt[N_ANCH];
__device__ unsigned long long g_state[NSTATE];

struct InPtrs { const float* cls[6]; const float* reg[6]; };

// ---------------- K1: decode (bit-exact vs reference) ----------------
__global__ void k_decode(InPtrs in) {
    int i = blockIdx.x * blockDim.x + threadIdx.x;
    if (i >= N_ANCH) return;
    const int offs[7]   = {0, 16384, 20480, 21504, 21760, 21824, 21840};
    const int maps[6]   = {128, 64, 32, 16, 8, 4};
    const float strd[6] = {4.f, 8.f, 16.f, 32.f, 64.f, 128.f};
    int sc = 0;
    #pragma unroll
    for (int k = 0; k < 5; k++) if (i >= offs[k + 1]) sc = k + 1;
    int local = i - offs[sc];
    int W = maps[sc];
    int y = local / W, x = local - y * W;
    int HW = W * W;
    const float* cls = in.cls[sc];
    const float* reg = in.reg[sc];

    float c0 = cls[local], c1 = cls[HW + local];
    float m  = fmaxf(c0, c1);
    float e0 = expf(__fsub_rn(c0, m));
    float e1 = expf(__fsub_rn(c1, m));
    float prob = __fdiv_rn(e1, __fadd_rn(e0, e1));

    float s   = strd[sc];
    float pwh = s * 4.0f;
    float pcx = __fadd_rn(0.5f * s, __fmul_rn((float)x, s));
    float pcy = __fadd_rn(0.5f * s, __fmul_rn((float)y, s));
    float l0 = reg[local], l1 = reg[HW + local];
    float l2 = reg[2 * HW + local], l3 = reg[3 * HW + local];
    float cx = __fadd_rn(pcx, __fmul_rn(__fmul_rn(l0, 0.1f), pwh));
    float cy = __fadd_rn(pcy, __fmul_rn(__fmul_rn(l1, 0.1f), pwh));
    float w  = __fmul_rn(pwh, expf(__fmul_rn(l2, 0.2f)));
    float h  = __fmul_rn(pwh, expf(__fmul_rn(l3, 0.2f)));
    float x1 = __fsub_rn(cx, __fmul_rn(w, 0.5f));
    float y1 = __fsub_rn(cy, __fmul_rn(h, 0.5f));
    float x2 = __fadd_rn(x1, w);
    float y2 = __fadd_rn(y1, h);

    g_x1[i] = x1; g_y1[i] = y1; g_x2[i] = x2; g_y2[i] = y2; g_sc[i] = prob;
    g_area[i] = __fmul_rn(__fadd_rn(__fsub_rn(x2, x1), 1.0f),
                          __fadd_rn(__fsub_rn(y2, y1), 1.0f));

    // sort key: ascending key == descending score; stable sort keeps idx order
    unsigned u   = __float_as_uint(prob);
    unsigned ord = (u & 0x80000000u) ? ~u : (u | 0x80000000u);
    g_keyA[i] = ~ord;
    g_valA[i] = (unsigned short)i;
}

// ---------------- radix sort: 4 passes of 8-bit, stable LSD ----------------
__global__ void k_hist(const unsigned* __restrict__ key, int shift) {
    __shared__ int h[256];
    int t = threadIdx.x;
    h[t] = 0;
    __syncthreads();
    int i = blockIdx.x * 256 + t;
    if (i < N_ANCH) atomicAdd(&h[(key[i] >> shift) & 255u], 1);
    __syncthreads();
    g_hist[blockIdx.x * 256 + t] = h[t];
}

__global__ void k_scanhist() {
    __shared__ int tot[256];
    int d = threadIdx.x;
    int run = 0;
    for (int b = 0; b < NBLK; b++) {
        int c = g_hist[b * 256 + d];
        g_off[b * 256 + d] = run;
        run += c;
    }
    tot[d] = run;
    __syncthreads();
    // inclusive scan over 256 digits
    int val = run;
    for (int s = 1; s < 256; s <<= 1) {
        int y = (d >= s) ? tot[d - s] : 0;
        __syncthreads();
        val += y;
        tot[d] = val;
        __syncthreads();
    }
    int base = val - run;  // exclusive
    for (int b = 0; b < NBLK; b++) g_off[b * 256 + d] += base;
}

__global__ void k_scatter(const unsigned* __restrict__ keyin,
                          const unsigned short* __restrict__ valin,
                          unsigned* __restrict__ keyout,
                          unsigned short* __restrict__ valout, int shift) {
    __shared__ int cnt[256];
    __shared__ int boff[256];
    int t = threadIdx.x;
    cnt[t] = 0;
    boff[t] = g_off[blockIdx.x * 256 + t];
    __syncthreads();
    int i = blockIdx.x * 256 + t;
    bool on = i < N_ANCH;
    unsigned k = 0; unsigned short v = 0;
    if (on) { k = keyin[i]; v = valin[i]; }
    unsigned d = (k >> shift) & 255u;
    int lane = t & 31, wid = t >> 5;
    unsigned wactive = __ballot_sync(FULLM, on);
    int lrank = 0;
    for (int w = 0; w < 8; w++) {
        if (wid == w && on) {
            unsigned peers = __match_any_sync(wactive, d);
            int leader = __ffs(peers) - 1;
            int gsz = __popc(peers);
            int old = 0;
            if (lane == leader) old = atomicAdd(&cnt[d], gsz);
            old = __shfl_sync(peers, old, leader);
            lrank = old + __popc(peers & ((1u << lane) - 1));
        }
        __syncthreads();
    }
    if (on) {
        int pos = boff[d] + lrank;
        keyout[pos] = k;
        valout[pos] = v;
    }
}

__global__ void k_srank() {
    int r = blockIdx.x * blockDim.x + threadIdx.x;
    if (r < N_ANCH) g_srank[g_valA[r]] = r;
}

// ---------------- tile bounding boxes (original index order) ----------------
__global__ void k_tilebb() {
    __shared__ float m0[64], m1[64], m2[64], m3[64], m4[64], m5[64];
    int t = threadIdx.x;
    int j = blockIdx.x * 64 + t;
    bool on = j < N_ANCH;
    float a = on ? g_area[j] : 0.f;
    m0[t] = on ? g_x1[j] :  1e30f;
    m1[t] = on ? g_y1[j] :  1e30f;
    m2[t] = on ? g_x2[j] : -1e30f;
    m3[t] = on ? g_y2[j] : -1e30f;
    m4[t] = on ? a :  1e30f;
    m5[t] = on ? a : -1e30f;
    for (int s = 32; s > 0; s >>= 1) {
        __syncthreads();
        if (t < s) {
            m0[t] = fminf(m0[t], m0[t + s]);
            m1[t] = fminf(m1[t], m1[t + s]);
            m2[t] = fmaxf(m2[t], m2[t + s]);
            m3[t] = fmaxf(m3[t], m3[t + s]);
            m4[t] = fminf(m4[t], m4[t + s]);
            m5[t] = fmaxf(m5[t], m5[t + s]);
        }
    }
    if (t == 0) {
        g_tminx1[blockIdx.x] = m0[0]; g_tminy1[blockIdx.x] = m1[0];
        g_tmaxx2[blockIdx.x] = m2[0]; g_tmaxy2[blockIdx.x] = m3[0];
        g_tamin[blockIdx.x]  = m4[0]; g_tamax[blockIdx.x]  = m5[0];
    }
}

// ---------------- sparse higher-ranked suppressor lists (warp per box) ----------------
__global__ void k_nbr() {
    int warp = (blockIdx.x * blockDim.x + threadIdx.x) >> 5;
    int lane = threadIdx.x & 31;
    if (warp >= N_ANCH) return;
    int i = warp;
    float sci = g_sc[i];
    if (sci <= CLS_THF) { if (lane == 0) g_ncnt[i] = 0; return; }
    float x1 = g_x1[i], y1 = g_y1[i], x2 = g_x2[i], y2 = g_y2[i], ai = g_area[i];
    int ri = g_srank[i];
    int cnt = 0;
    for (int tb = 0; tb < NTILE; tb += 32) {
        int t = tb + lane;
        bool act = false;
        if (t < NTILE) {
            float bw = __fadd_rn(__fsub_rn(fminf(x2, g_tmaxx2[t]), fmaxf(x1, g_tminx1[t])), 1.0f);
            float bh = __fadd_rn(__fsub_rn(fminf(y2, g_tmaxy2[t]), fmaxf(y1, g_tminy1[t])), 1.0f);
            float lo = fminf(ai, g_tamax[t]);
            float hi = fmaxf(ai, g_tamin[t]);
            act = (bw > 0.f) && (bh > 0.f) && (lo > 0.299f * hi);  // conservative
        }
        unsigned bal = __ballot_sync(FULLM, act);
        while (bal) {
            int tt = __ffs(bal) - 1;
            bal &= bal - 1;
            int j0 = (tb + tt) << 6;
            #pragma unroll
            for (int h = 0; h < 2; h++) {
                int j = j0 + h * 32 + lane;
                bool hit = false;
                unsigned short rjv = 0;
                if (j < N_ANCH) {
                    float xx1 = fmaxf(x1, g_x1[j]);
                    float yy1 = fmaxf(y1, g_y1[j]);
                    float xx2 = fminf(x2, g_x2[j]);
                    float yy2 = fminf(y2, g_y2[j]);
                    float w  = fmaxf(__fadd_rn(__fsub_rn(xx2, xx1), 1.f), 0.f);
                    float hh = fmaxf(__fadd_rn(__fsub_rn(yy2, yy1), 1.f), 0.f);
                    float inter = __fmul_rn(w, hh);
                    float aj = g_area[j];
                    if (inter > 0.299f * fmaxf(ai, aj)) {        // conservative prefilter
                        float iou = __fdiv_rn(inter, __fsub_rn(__fadd_rn(ai, aj), inter));
                        if (iou > NMS_THF) {
                            int rj = g_srank[j];
                            if (rj < ri && g_sc[j] > CLS_THF) { hit = true; rjv = (unsigned short)rj; }
                        }
                    }
                }
                unsigned hb = __ballot_sync(FULLM, hit);
                if (hit) {
                    int off = cnt + __popc(hb & ((1u << lane) - 1));
                    if (off < CAP) g_nbr[(size_t)i * CAP + off] = rjv;
                }
                cnt += __popc(hb);
            }
        }
    }
    if (lane == 0) g_ncnt[i] = min(cnt, CAP);
}

// ---------------- parallel fixed-point NMS resolve ----------------
// state: 2 bits per sorted rank r: bit0 = resolved, bit1 = kept
__global__ void __launch_bounds__(1024) k_resolve() {
    __shared__ unsigned long long state[NSTATE];
    __shared__ int more;
    int t = threadIdx.x;
    for (int w = t; w < NSTATE; w += 1024) {
        unsigned long long sw = 0;
        int base = w << 5;
        for (int b = 0; b < 32; b++) {
            int r = base + b;
            bool valid = false;
            if (r < N_ANCH) {
                int o = g_valA[r];
                valid = g_sc[o] > CLS_THF;
            }
            if (!valid) sw |= 1ull << (2 * b);   // invalid => resolved, not kept
        }
        state[w] = sw;
    }
    if (t == 0) more = 0;
    __syncthreads();

    for (;;) {
        int lm = 0;
        for (int r = t; r < N_ANCH; r += 1024) {
            unsigned long long sv = state[r >> 5] >> ((r & 31) * 2);
            if (sv & 1ull) continue;   // already resolved
            int o = g_valA[r];
            int cn = g_ncnt[o];
            const unsigned short* lst = g_nbr + (size_t)o * CAP;
            bool anyk = false, allres = true;
            for (int e = 0; e < cn; e++) {
                int cr = lst[e];
                unsigned long long cs = state[cr >> 5] >> ((cr & 31) * 2);
                if (cs & 2ull) { anyk = true; break; }   // kept higher nbr => removed
                if (!(cs & 1ull)) allres = false;
            }
            if (anyk)
                atomicOr(&state[r >> 5], 1ull << ((r & 31) * 2));
            else if (allres)
                atomicOr(&state[r >> 5], 3ull << ((r & 31) * 2));
            else
                lm = 1;
        }
        if (lm) more = 1;
        __syncthreads();
        int m = more;
        __syncthreads();
        if (!m) break;
        if (t == 0) more = 0;
        __syncthreads();
    }
    for (int w = t; w < NSTATE; w += 1024) g_state[w] = state[w];
}

// ---------------- final masked write ----------------
__global__ void k_final(float* __restrict__ out) {
    int i = blockIdx.x * blockDim.x + threadIdx.x;
    if (i >= N_ANCH) return;
    float sc = g_sc[i];
    int r = g_srank[i];
    unsigned long long sv = g_state[r >> 5] >> ((r & 31) * 2);
    bool kp = ((sv >> 1) & 1ull) && (sc > FIN_THF);
    float f = kp ? 1.0f : 0.0f;
    out[i * 5 + 0] = __fmul_rn(g_x1[i], f);
    out[i * 5 + 1] = __fmul_rn(g_y1[i], f);
    out[i * 5 + 2] = __fmul_rn(g_x2[i], f);
    out[i * 5 + 3] = __fmul_rn(g_y2[i], f);
    out[i * 5 + 4] = __fmul_rn(sc, f);
}

extern "C" void kernel_launch(void* const* d_in, const int* in_sizes, int n_in,
                              void* d_out, int out_size) {
    (void)in_sizes; (void)n_in; (void)out_size;
    InPtrs p;
    for (int i = 0; i < 6; i++) {
        p.cls[i] = (const float*)d_in[2 * i];
        p.reg[i] = (const float*)d_in[2 * i + 1];
    }
    // resolve device symbol addresses (host-side; cheap, capture-safe)
    unsigned *kA, *kB; unsigned short *vA, *vB;
    cudaGetSymbolAddress((void**)&kA, g_keyA);
    cudaGetSymbolAddress((void**)&kB, g_keyB);
    cudaGetSymbolAddress((void**)&vA, g_valA);
    cudaGetSymbolAddress((void**)&vB, g_valB);

    k_decode<<<NBLK, 256>>>(p);
    k_tilebb<<<NTILE, 64>>>();

    // stable LSD radix: pass shifts 0,8,16,24 (A->B->A->B->A)
    k_hist<<<NBLK, 256>>>(kA, 0);
    k_scanhist<<<1, 256>>>();
    k_scatter<<<NBLK, 256>>>(kA, vA, kB, vB, 0);
    k_hist<<<NBLK, 256>>>(kB, 8);
    k_scanhist<<<1, 256>>>();
    k_scatter<<<NBLK, 256>>>(kB, vB, kA, vA, 8);
    k_hist<<<NBLK, 256>>>(kA, 16);
    k_scanhist<<<1, 256>>>();
    k_scatter<<<NBLK, 256>>>(kA, vA, kB, vB, 16);
    k_hist<<<NBLK, 256>>>(kB, 24);
    k_scanhist<<<1, 256>>>();
    k_scatter<<<NBLK, 256>>>(kB, vB, kA, vA, 24);

    k_srank<<<NBLK, 256>>>();
    k_nbr<<<(N_ANCH * 32 + 255) / 256, 256>>>();
    k_resolve<<<1, 1024>>>();
    k_final<<<NBLK, 256>>>((float*)d_out);
}